// round 11
// baseline (speedup 1.0000x reference)
#include <cuda_runtime.h>
#include <cuda_fp16.h>
#include <mma.h>
#include <cstdint>

using namespace nvcuda;

// ---------------- problem constants ----------------
constexpr int D_MODEL = 1024;
constexpr int N_HEADS = 16;
constexpr int D_FF    = 4096;
constexpr int BATCH   = 4;
constexpr int SEQ     = 2048;
constexpr int TOK     = BATCH * SEQ;   // 8192

// ---------------- scratch (device globals; no allocation allowed) ----------------
__device__ __half g_h  [(size_t)TOK * D_MODEL];
__device__ __half g_q  [(size_t)TOK * D_MODEL];
__device__ __half g_k  [(size_t)TOK * D_MODEL];
__device__ __half g_v  [(size_t)TOK * D_MODEL];
__device__ __half g_ctx[(size_t)TOK * D_MODEL];
__device__ __half g_f1 [(size_t)TOK * D_FF];
__device__ float  g_x1 [(size_t)TOK * D_MODEL];
__device__ __half g_wq [(size_t)D_MODEL * D_MODEL];
__device__ __half g_wk [(size_t)D_MODEL * D_MODEL];
__device__ __half g_wv [(size_t)D_MODEL * D_MODEL];
__device__ __half g_wo [(size_t)D_MODEL * D_MODEL];
__device__ __half g_w1 [(size_t)D_FF * D_MODEL];
__device__ __half g_w2 [(size_t)D_MODEL * D_FF];

// ================= cp.async =================
#define CP_ASYNC16(dst, src) \
    asm volatile("cp.async.cg.shared.global [%0], [%1], 16;" :: "r"(dst), "l"(src))
#define CP_COMMIT() asm volatile("cp.async.commit_group;")
#define CP_WAIT1()  asm volatile("cp.async.wait_group 1;")
#define CP_WAIT2()  asm volatile("cp.async.wait_group 2;")

__device__ __forceinline__ uint32_t smem_u32(const void* p) {
    uint32_t a;
    asm("{ .reg .u64 t; cvta.to.shared.u64 t, %1; cvt.u32.u64 %0, t; }" : "=r"(a) : "l"(p));
    return a;
}

// ============================================================
// fused weight fp32 -> fp16 conversion (single launch, all 6 weights)
// element layout: wq[0,1M) wk[1M,2M) wv[2M,3M) wo[3M,4M) w1[4M,8M) w2[8M,12M)
// ============================================================
constexpr int NW1 = D_MODEL * D_MODEL;       // 1048576
constexpr int NW2 = D_FF * D_MODEL;          // 4194304
constexpr int NW_TOT = 4 * NW1 + 2 * NW2;    // 12582912

__global__ void __launch_bounds__(256) f2h_all_kernel(
    const float* __restrict__ wq, const float* __restrict__ wk,
    const float* __restrict__ wv, const float* __restrict__ wo,
    const float* __restrict__ w1, const float* __restrict__ w2)
{
    int e = (blockIdx.x * 256 + threadIdx.x) * 4;
    if (e >= NW_TOT) return;
    const float* s;
    __half* d;
    int off;
    if (e < 4 * NW1) {
        int seg = e >> 20;                    // NW1 = 1<<20
        off = e & (NW1 - 1);
        switch (seg) {
            case 0:  s = wq; break;
            case 1:  s = wk; break;
            case 2:  s = wv; break;
            default: s = wo; break;
        }
        __half* dst[4] = {g_wq, g_wk, g_wv, g_wo};
        d = dst[seg];
    } else if (e < 4 * NW1 + NW2) {
        s = w1; d = g_w1; off = e - 4 * NW1;
    } else {
        s = w2; d = g_w2; off = e - 4 * NW1 - NW2;
    }
    float4 v = *(const float4*)(s + off);
    union { __half2 h[2]; uint2 u; } c;
    c.h[0] = __floats2half2_rn(v.x, v.y);
    c.h[1] = __floats2half2_rn(v.z, v.w);
    *(uint2*)(d + off) = c.u;
}

// ============================================================
// LayerNorm (torch semantics: ddof=1, /(std+eps)) fp32 in -> fp16 out
// ============================================================
__global__ void __launch_bounds__(256) ln_kernel(
    const float* __restrict__ x, const float* __restrict__ ga,
    const float* __restrict__ gb, __half* __restrict__ y)
{
    int row = blockIdx.x;
    const float4 v = ((const float4*)(x + (size_t)row * D_MODEL))[threadIdx.x];

    __shared__ float red[32];
    int lane = threadIdx.x & 31, wid = threadIdx.x >> 5;

    float s = v.x + v.y + v.z + v.w;
    #pragma unroll
    for (int o = 16; o; o >>= 1) s += __shfl_down_sync(0xffffffffu, s, o);
    if (lane == 0) red[wid] = s;
    __syncthreads();
    if (wid == 0) {
        float t = (lane < 8) ? red[lane] : 0.f;
        #pragma unroll
        for (int o = 4; o; o >>= 1) t += __shfl_down_sync(0xffffffffu, t, o);
        if (lane == 0) red[0] = t;
    }
    __syncthreads();
    float mean = red[0] * (1.f / 1024.f);

    float dx = v.x - mean, dy = v.y - mean, dz = v.z - mean, dw = v.w - mean;
    float s2 = dx*dx + dy*dy + dz*dz + dw*dw;
    #pragma unroll
    for (int o = 16; o; o >>= 1) s2 += __shfl_down_sync(0xffffffffu, s2, o);
    __syncthreads();
    if (lane == 0) red[wid] = s2;
    __syncthreads();
    if (wid == 0) {
        float t = (lane < 8) ? red[lane] : 0.f;
        #pragma unroll
        for (int o = 4; o; o >>= 1) t += __shfl_down_sync(0xffffffffu, t, o);
        if (lane == 0) red[0] = t;
    }
    __syncthreads();
    float var = red[0] * (1.f / 1023.f);
    float inv = 1.f / (sqrtf(var) + 1e-5f);
    float a = ga[0] * inv, b0 = gb[0];

    union { __half2 h[2]; uint2 u; } c;
    c.h[0] = __floats2half2_rn(a*dx + b0, a*dy + b0);
    c.h[1] = __floats2half2_rn(a*dz + b0, a*dw + b0);
    ((uint2*)(y + (size_t)row * D_MODEL))[threadIdx.x] = c.u;
}

// ============================================================
// fp16 HMMA GEMM: C[M,N] = A[M,K] * W[N,K]^T + bias ...
// CTA tile 128x128, BK=64, 3-stage cp.async pipeline, 256 threads.
// (unchanged from round-8 passing kernel)
// ============================================================
constexpr int BM = 128, BN = 128, BK = 64;
constexpr int LDS = 72;
constexpr int TILE_HALVES = 128 * LDS;
constexpr int STAGE_BYTES = 2 * TILE_HALVES * 2;
constexpr int G_STAGES = 3;
constexpr int G_SMEM = G_STAGES * STAGE_BYTES;            // 110592

template<int EPI>
__global__ void __launch_bounds__(256) gemm_h(
    const __half* __restrict__ A, const __half* __restrict__ W,
    const float* __restrict__ bias, const float* __restrict__ resid,
    float* __restrict__ Cf, __half* __restrict__ Ch, int N, int K)
{
    extern __shared__ __align__(16) char smraw[];
    __half* sm = (__half*)smraw;
    const uint32_t smb = smem_u32(sm);

    const int tid = threadIdx.x;
    const int m0 = blockIdx.y * BM, n0 = blockIdx.x * BN;
    const int KT = K >> 6;

    auto fill = [&](int kb) {
        const int st = kb % G_STAGES;
        const uint32_t sA = smb + st * STAGE_BYTES;
        const uint32_t sB = sA + TILE_HALVES * 2;
        const __half* gA = A + (size_t)m0 * K + kb * BK;
        const __half* gB = W + (size_t)n0 * K + kb * BK;
        #pragma unroll
        for (int i = 0; i < 4; i++) {
            int lin = i * 256 + tid, r = lin >> 3, c = lin & 7;
            CP_ASYNC16(sA + r * (LDS * 2) + c * 16, gA + (size_t)r * K + c * 8);
        }
        #pragma unroll
        for (int i = 0; i < 4; i++) {
            int lin = i * 256 + tid, r = lin >> 3, c = lin & 7;
            CP_ASYNC16(sB + r * (LDS * 2) + c * 16, gB + (size_t)r * K + c * 8);
        }
        CP_COMMIT();
    };

    const int warp = tid >> 5, wm = warp >> 1, wn = warp & 1;

    wmma::fragment<wmma::accumulator, 16, 16, 16, float> cf[2][4];
    #pragma unroll
    for (int i = 0; i < 2; i++)
        #pragma unroll
        for (int j = 0; j < 4; j++) wmma::fill_fragment(cf[i][j], 0.f);

    fill(0); fill(1); fill(2);

    for (int kb = 0; kb < KT; kb++) {
        const int st = kb % G_STAGES;
        CP_WAIT2();
        __syncthreads();

        const __half* As = sm + st * (STAGE_BYTES / 2) + (wm * 32) * LDS;
        const __half* Bs = sm + st * (STAGE_BYTES / 2) + TILE_HALVES + (wn * 64) * LDS;

        #pragma unroll
        for (int kk = 0; kk < 4; kk++) {
            wmma::fragment<wmma::matrix_a, 16, 16, 16, __half, wmma::row_major> af[2];
            #pragma unroll
            for (int mi = 0; mi < 2; mi++)
                wmma::load_matrix_sync(af[mi], As + (mi * 16) * LDS + kk * 16, LDS);
            #pragma unroll
            for (int nj = 0; nj < 4; nj++) {
                wmma::fragment<wmma::matrix_b, 16, 16, 16, __half, wmma::col_major> bf;
                wmma::load_matrix_sync(bf, Bs + (nj * 16) * LDS + kk * 16, LDS);
                #pragma unroll
                for (int mi = 0; mi < 2; mi++)
                    wmma::mma_sync(cf[mi][nj], af[mi], bf, cf[mi][nj]);
            }
        }
        __syncthreads();
        if (kb + G_STAGES < KT) fill(kb + G_STAGES); else CP_COMMIT();
    }

    float* Cs = (float*)sm;
    constexpr int LDC = 136;
    #pragma unroll
    for (int mi = 0; mi < 2; mi++)
        #pragma unroll
        for (int nj = 0; nj < 4; nj++)
            wmma::store_matrix_sync(Cs + (wm*32 + mi*16) * LDC + wn*64 + nj*16,
                                    cf[mi][nj], LDC, wmma::mem_row_major);
    __syncthreads();

    #pragma unroll
    for (int i = 0; i < 16; i++) {
        int lin = i * 256 + tid, r = lin >> 5, c4 = lin & 31;
        float4 v = *(float4*)(Cs + r * LDC + c4 * 4);
        float4 bv = *(const float4*)(bias + n0 + c4 * 4);
        v.x += bv.x; v.y += bv.y; v.z += bv.z; v.w += bv.w;
        if (EPI == 1) {
            v.x = fmaxf(v.x, 0.f); v.y = fmaxf(v.y, 0.f);
            v.z = fmaxf(v.z, 0.f); v.w = fmaxf(v.w, 0.f);
        }
        if (EPI == 2) {
            float4 rv = *(const float4*)(resid + (size_t)(m0 + r) * N + n0 + c4 * 4);
            v.x += rv.x; v.y += rv.y; v.z += rv.z; v.w += rv.w;
            *(float4*)(Cf + (size_t)(m0 + r) * N + n0 + c4 * 4) = v;
        } else {
            union { __half2 h[2]; uint2 u; } stv;
            stv.h[0] = __floats2half2_rn(v.x, v.y);
            stv.h[1] = __floats2half2_rn(v.z, v.w);
            *(uint2*)(Ch + (size_t)(m0 + r) * N + n0 + c4 * 4) = stv.u;
        }
    }
}

// ============================================================
// Flash attention, fp16 wmma, fp32 softmax/accum.
// cp.async 2-stage double-buffered K/V tiles.
// grid = (SEQ/64, BATCH*N_HEADS), 128 threads (4 warps).
// ============================================================
constexpr int LDH = 72;   // half row stride
constexpr int LDF = 68;   // float row stride
// Qs 9216 + Ps 9216 + K/V 2 stages (2*2*9216=36864) + Ss 17408 + Os 17408 + ml/ll 512
constexpr int ATTN_SMEM = 9216 + 9216 + 36864 + 17408 + 17408 + 512;  // 90624

__global__ void __launch_bounds__(128) attn_kernel(
    const __half* __restrict__ Q, const __half* __restrict__ K,
    const __half* __restrict__ V, __half* __restrict__ O)
{
    extern __shared__ __align__(16) char sm[];
    __half* Qs  = (__half*)(sm);
    __half* Ps  = Qs + 64 * LDH;
    __half* KVs = Ps + 64 * LDH;            // [stage][K|V] each 64*LDH halves
    float*  Ss  = (float*)(KVs + 4 * 64 * LDH);
    float*  Os  = Ss + 64 * LDF;
    float*  Ml  = Os + 64 * LDF;
    float*  Ll  = Ml + 64;
    const uint32_t kv_base = smem_u32(KVs);

    const int tid = threadIdx.x;
    const int b = blockIdx.y >> 4, h = blockIdx.y & 15;
    const size_t base = (size_t)b * SEQ * D_MODEL + (size_t)h * 64;
    const int q0 = blockIdx.x * 64;
    const __half2 qs2 = __floats2half2_rn(0.125f, 0.125f);
    constexpr int NT = SEQ / 64;

    // async prefetch of K/V tile kt into stage kt&1
    auto fill = [&](int kt) {
        const int st = kt & 1;
        const uint32_t sK = kv_base + st * (2 * 64 * LDH * 2);
        const uint32_t sV = sK + 64 * LDH * 2;
        const int k0 = kt * 64;
        #pragma unroll
        for (int i = 0; i < 4; i++) {
            int lin = i * 128 + tid, r = lin >> 3, c = lin & 7;
            CP_ASYNC16(sK + r * (LDH * 2) + c * 16,
                       K + base + (size_t)(k0 + r) * D_MODEL + c * 8);
        }
        #pragma unroll
        for (int i = 0; i < 4; i++) {
            int lin = i * 128 + tid, r = lin >> 3, c = lin & 7;
            CP_ASYNC16(sV + r * (LDH * 2) + c * 16,
                       V + base + (size_t)(k0 + r) * D_MODEL + c * 8);
        }
    };

    // load Q (scaled by exact 1/8), init O/m/l
    #pragma unroll
    for (int i = 0; i < 4; i++) {
        int lin = i * 128 + tid, r = lin >> 3, c = lin & 7;
        union { __half2 h[4]; uint4 u; } v;
        v.u = *(const uint4*)(Q + base + (size_t)(q0 + r) * D_MODEL + c * 8);
        #pragma unroll
        for (int t = 0; t < 4; t++) v.h[t] = __hmul2(v.h[t], qs2);
        *(uint4*)(Qs + r * LDH + c * 8) = v.u;
    }
    #pragma unroll
    for (int i = 0; i < 8; i++) {
        int lin = i * 128 + tid, r = lin >> 4, c4 = lin & 15;
        *(float4*)(Os + r * LDF + c4 * 4) = make_float4(0.f, 0.f, 0.f, 0.f);
    }
    if (tid < 64) { Ml[tid] = -1e30f; Ll[tid] = 0.f; }

    fill(0); CP_COMMIT();
    __syncthreads();

    const int w = tid >> 5;

    for (int kt = 0; kt < NT; kt++) {
        const int st = kt & 1;
        if (kt + 1 < NT) fill(kt + 1);
        CP_COMMIT();
        CP_WAIT1();          // tile kt resident; tile kt+1 may be in flight
        __syncthreads();

        const __half* Ks = KVs + st * (2 * 64 * LDH);
        const __half* Vs = Ks + 64 * LDH;

        // S = Qs * Ks^T  (warp: 16 q-rows x 64 keys)
        {
            wmma::fragment<wmma::accumulator, 16, 16, 16, float> sf[4];
            #pragma unroll
            for (int nj = 0; nj < 4; nj++) wmma::fill_fragment(sf[nj], 0.f);
            #pragma unroll
            for (int kk = 0; kk < 4; kk++) {
                wmma::fragment<wmma::matrix_a, 16, 16, 16, __half, wmma::row_major> af;
                wmma::load_matrix_sync(af, Qs + (w * 16) * LDH + kk * 16, LDH);
                #pragma unroll
                for (int nj = 0; nj < 4; nj++) {
                    wmma::fragment<wmma::matrix_b, 16, 16, 16, __half, wmma::col_major> bf;
                    wmma::load_matrix_sync(bf, Ks + (nj * 16) * LDH + kk * 16, LDH);
                    wmma::mma_sync(sf[nj], af, bf, sf[nj]);
                }
            }
            #pragma unroll
            for (int nj = 0; nj < 4; nj++)
                wmma::store_matrix_sync(Ss + (w * 16) * LDF + nj * 16, sf[nj], LDF,
                                        wmma::mem_row_major);
        }
        __syncthreads();

        // online softmax: 2 threads/row, write P in fp16
        {
            const int row = tid >> 1, hh = tid & 1;
            float* sr = Ss + row * LDF + hh * 32;
            __half* pr = Ps + row * LDH + hh * 32;
            float mx = -1e30f;
            #pragma unroll 8
            for (int c = 0; c < 32; c++) mx = fmaxf(mx, sr[c]);
            mx = fmaxf(mx, __shfl_xor_sync(0xffffffffu, mx, 1));
            const float mold = Ml[row];
            const float mnew = fmaxf(mold, mx);
            const float fac = __expf(mold - mnew);
            float ssum = 0.f;
            #pragma unroll 8
            for (int c = 0; c < 32; c++) {
                float e = __expf(sr[c] - mnew);
                pr[c] = __float2half(e);
                ssum += e;
            }
            ssum += __shfl_xor_sync(0xffffffffu, ssum, 1);
            float* orow = Os + row * LDF + hh * 32;
            #pragma unroll 8
            for (int c = 0; c < 32; c++) orow[c] *= fac;
            if (hh == 0) { Ml[row] = mnew; Ll[row] = Ll[row] * fac + ssum; }
        }
        __syncthreads();

        // O += P * V
        {
            #pragma unroll
            for (int nj = 0; nj < 4; nj++) {
                wmma::fragment<wmma::accumulator, 16, 16, 16, float> of;
                wmma::load_matrix_sync(of, Os + (w * 16) * LDF + nj * 16, LDF,
                                       wmma::mem_row_major);
                #pragma unroll
                for (int kk = 0; kk < 4; kk++) {
                    wmma::fragment<wmma::matrix_a, 16, 16, 16, __half, wmma::row_major> af;
                    wmma::load_matrix_sync(af, Ps + (w * 16) * LDH + kk * 16, LDH);
                    wmma::fragment<wmma::matrix_b, 16, 16, 16, __half, wmma::row_major> bf;
                    wmma::load_matrix_sync(bf, Vs + (kk * 16) * LDH + nj * 16, LDH);
                    wmma::mma_sync(of, af, bf, of);
                }
                wmma::store_matrix_sync(Os + (w * 16) * LDF + nj * 16, of, LDF,
                                        wmma::mem_row_major);
            }
        }
        __syncthreads();
    }

    // normalize + store fp16
    {
        const int row = tid >> 1, hh = tid & 1;
        const float inv = 1.f / Ll[row];
        #pragma unroll
        for (int c4 = 0; c4 < 8; c4++) {
            float4 v = *(float4*)(Os + row * LDF + hh * 32 + c4 * 4);
            union { __half2 h[2]; uint2 u; } st;
            st.h[0] = __floats2half2_rn(v.x * inv, v.y * inv);
            st.h[1] = __floats2half2_rn(v.z * inv, v.w * inv);
            *(uint2*)(O + base + (size_t)(q0 + row) * D_MODEL + hh * 32 + c4 * 4) = st.u;
        }
    }
}

// ============================================================
// launcher
// ============================================================
extern "C" void kernel_launch(void* const* d_in, const int* in_sizes, int n_in,
                              void* d_out, int out_size)
{
    const float* x    = (const float*)d_in[0];
    const float* wq   = (const float*)d_in[2];
    const float* bq   = (const float*)d_in[3];
    const float* wk   = (const float*)d_in[4];
    const float* bk   = (const float*)d_in[5];
    const float* wv   = (const float*)d_in[6];
    const float* bv   = (const float*)d_in[7];
    const float* wo   = (const float*)d_in[8];
    const float* bo   = (const float*)d_in[9];
    const float* w1   = (const float*)d_in[10];
    const float* b1   = (const float*)d_in[11];
    const float* w2   = (const float*)d_in[12];
    const float* b2   = (const float*)d_in[13];
    const float* ln1a = (const float*)d_in[14];
    const float* ln1b = (const float*)d_in[15];
    const float* ln2a = (const float*)d_in[16];
    const float* ln2b = (const float*)d_in[17];
    float* out = (float*)d_out;

    void* p;
    cudaGetSymbolAddress(&p, g_h);   __half* h   = (__half*)p;
    cudaGetSymbolAddress(&p, g_q);   __half* q   = (__half*)p;
    cudaGetSymbolAddress(&p, g_k);   __half* k   = (__half*)p;
    cudaGetSymbolAddress(&p, g_v);   __half* v   = (__half*)p;
    cudaGetSymbolAddress(&p, g_ctx); __half* ctx = (__half*)p;
    cudaGetSymbolAddress(&p, g_f1);  __half* f1  = (__half*)p;
    cudaGetSymbolAddress(&p, g_x1);  float*  x1  = (float*)p;

    cudaFuncSetAttribute(gemm_h<0>, cudaFuncAttributeMaxDynamicSharedMemorySize, G_SMEM);
    cudaFuncSetAttribute(gemm_h<1>, cudaFuncAttributeMaxDynamicSharedMemorySize, G_SMEM);
    cudaFuncSetAttribute(gemm_h<2>, cudaFuncAttributeMaxDynamicSharedMemorySize, G_SMEM);
    cudaFuncSetAttribute(attn_kernel, cudaFuncAttributeMaxDynamicSharedMemorySize, ATTN_SMEM);

    __half* wqh; __half* wkh; __half* wvh; __half* woh; __half* w1h; __half* w2h;
    cudaGetSymbolAddress(&p, g_wq); wqh = (__half*)p;
    cudaGetSymbolAddress(&p, g_wk); wkh = (__half*)p;
    cudaGetSymbolAddress(&p, g_wv); wvh = (__half*)p;
    cudaGetSymbolAddress(&p, g_wo); woh = (__half*)p;
    cudaGetSymbolAddress(&p, g_w1); w1h = (__half*)p;
    cudaGetSymbolAddress(&p, g_w2); w2h = (__half*)p;

    // launch 0: all weights -> fp16 (single launch)
    f2h_all_kernel<<<NW_TOT / 1024, 256>>>(wq, wk, wv, wo, w1, w2);

    // launch 1: LN1 -> h (fp16)
    ln_kernel<<<TOK, 256>>>(x, ln1a, ln1b, h);

    // launches 2-4: QKV projections (fp16 out)
    dim3 g1024(D_MODEL / 128, TOK / 128);
    gemm_h<0><<<g1024, 256, G_SMEM>>>(h, wqh, bq, nullptr, nullptr, q, D_MODEL, D_MODEL);
    gemm_h<0><<<g1024, 256, G_SMEM>>>(h, wkh, bk, nullptr, nullptr, k, D_MODEL, D_MODEL);
    gemm_h<0><<<g1024, 256, G_SMEM>>>(h, wvh, bv, nullptr, nullptr, v, D_MODEL, D_MODEL);

    // launch 5: attention -> ctx (fp16)   [ncu -s 5 -c 1 captures this]
    attn_kernel<<<dim3(SEQ / 64, BATCH * N_HEADS), 128, ATTN_SMEM>>>(q, k, v, ctx);

    // launch 6: W_O + residual -> x1 (fp32)
    gemm_h<2><<<g1024, 256, G_SMEM>>>(ctx, woh, bo, x, x1, nullptr, D_MODEL, D_MODEL);

    // launch 7: LN2 -> h (fp16)
    ln_kernel<<<TOK, 256>>>(x1, ln2a, ln2b, h);

    // launches 8-9: FFN
    gemm_h<1><<<dim3(D_FF / 128, TOK / 128), 256, G_SMEM>>>(h, w1h, b1, nullptr, nullptr, f1, D_FF, D_MODEL);
    gemm_h<2><<<g1024, 256, G_SMEM>>>(f1, w2h, b2, x1, out, nullptr, D_MODEL, D_FF);
}

// round 12
// speedup vs baseline: 1.0099x; 1.0099x over previous
#include <cuda_runtime.h>
#include <cuda_fp16.h>
#include <mma.h>
#include <cstdint>

using namespace nvcuda;

// ---------------- problem constants ----------------
constexpr int D_MODEL = 1024;
constexpr int N_HEADS = 16;
constexpr int D_FF    = 4096;
constexpr int BATCH   = 4;
constexpr int SEQ     = 2048;
constexpr int TOK     = BATCH * SEQ;   // 8192

// ---------------- scratch (device globals; no allocation allowed) ----------------
__device__ __half g_h  [(size_t)TOK * D_MODEL];
__device__ __half g_q  [(size_t)TOK * D_MODEL];
__device__ __half g_k  [(size_t)TOK * D_MODEL];
__device__ __half g_v  [(size_t)TOK * D_MODEL];
__device__ __half g_ctx[(size_t)TOK * D_MODEL];
__device__ __half g_f1 [(size_t)TOK * D_FF];
__device__ float  g_x1 [(size_t)TOK * D_MODEL];
__device__ __half g_wq [(size_t)D_MODEL * D_MODEL];
__device__ __half g_wk [(size_t)D_MODEL * D_MODEL];
__device__ __half g_wv [(size_t)D_MODEL * D_MODEL];
__device__ __half g_wo [(size_t)D_MODEL * D_MODEL];
__device__ __half g_w1 [(size_t)D_FF * D_MODEL];
__device__ __half g_w2 [(size_t)D_MODEL * D_FF];

// ================= cp.async =================
#define CP_ASYNC16(dst, src) \
    asm volatile("cp.async.cg.shared.global [%0], [%1], 16;" :: "r"(dst), "l"(src))
#define CP_COMMIT() asm volatile("cp.async.commit_group;")
#define CP_WAIT1()  asm volatile("cp.async.wait_group 1;")

__device__ __forceinline__ uint32_t smem_u32(const void* p) {
    uint32_t a;
    asm("{ .reg .u64 t; cvta.to.shared.u64 t, %1; cvt.u32.u64 %0, t; }" : "=r"(a) : "l"(p));
    return a;
}

// ============================================================
// fused weight fp32 -> fp16 conversion (single launch, all 6 weights)
// ============================================================
constexpr int NW1 = D_MODEL * D_MODEL;       // 1048576
constexpr int NW2 = D_FF * D_MODEL;          // 4194304
constexpr int NW_TOT = 4 * NW1 + 2 * NW2;    // 12582912

__global__ void __launch_bounds__(256) f2h_all_kernel(
    const float* __restrict__ wq, const float* __restrict__ wk,
    const float* __restrict__ wv, const float* __restrict__ wo,
    const float* __restrict__ w1, const float* __restrict__ w2)
{
    int e = (blockIdx.x * 256 + threadIdx.x) * 4;
    if (e >= NW_TOT) return;
    const float* s;
    __half* d;
    int off;
    if (e < 4 * NW1) {
        int seg = e >> 20;                    // NW1 = 1<<20
        off = e & (NW1 - 1);
        switch (seg) {
            case 0:  s = wq; break;
            case 1:  s = wk; break;
            case 2:  s = wv; break;
            default: s = wo; break;
        }
        __half* dst[4] = {g_wq, g_wk, g_wv, g_wo};
        d = dst[seg];
    } else if (e < 4 * NW1 + NW2) {
        s = w1; d = g_w1; off = e - 4 * NW1;
    } else {
        s = w2; d = g_w2; off = e - 4 * NW1 - NW2;
    }
    float4 v = *(const float4*)(s + off);
    union { __half2 h[2]; uint2 u; } c;
    c.h[0] = __floats2half2_rn(v.x, v.y);
    c.h[1] = __floats2half2_rn(v.z, v.w);
    *(uint2*)(d + off) = c.u;
}

// ============================================================
// LayerNorm (torch semantics: ddof=1, /(std+eps)) fp32 in -> fp16 out
// ============================================================
__global__ void __launch_bounds__(256) ln_kernel(
    const float* __restrict__ x, const float* __restrict__ ga,
    const float* __restrict__ gb, __half* __restrict__ y)
{
    int row = blockIdx.x;
    const float4 v = ((const float4*)(x + (size_t)row * D_MODEL))[threadIdx.x];

    __shared__ float red[32];
    int lane = threadIdx.x & 31, wid = threadIdx.x >> 5;

    float s = v.x + v.y + v.z + v.w;
    #pragma unroll
    for (int o = 16; o; o >>= 1) s += __shfl_down_sync(0xffffffffu, s, o);
    if (lane == 0) red[wid] = s;
    __syncthreads();
    if (wid == 0) {
        float t = (lane < 8) ? red[lane] : 0.f;
        #pragma unroll
        for (int o = 4; o; o >>= 1) t += __shfl_down_sync(0xffffffffu, t, o);
        if (lane == 0) red[0] = t;
    }
    __syncthreads();
    float mean = red[0] * (1.f / 1024.f);

    float dx = v.x - mean, dy = v.y - mean, dz = v.z - mean, dw = v.w - mean;
    float s2 = dx*dx + dy*dy + dz*dz + dw*dw;
    #pragma unroll
    for (int o = 16; o; o >>= 1) s2 += __shfl_down_sync(0xffffffffu, s2, o);
    __syncthreads();
    if (lane == 0) red[wid] = s2;
    __syncthreads();
    if (wid == 0) {
        float t = (lane < 8) ? red[lane] : 0.f;
        #pragma unroll
        for (int o = 4; o; o >>= 1) t += __shfl_down_sync(0xffffffffu, t, o);
        if (lane == 0) red[0] = t;
    }
    __syncthreads();
    float var = red[0] * (1.f / 1023.f);
    float inv = 1.f / (sqrtf(var) + 1e-5f);
    float a = ga[0] * inv, b0 = gb[0];

    union { __half2 h[2]; uint2 u; } c;
    c.h[0] = __floats2half2_rn(a*dx + b0, a*dy + b0);
    c.h[1] = __floats2half2_rn(a*dz + b0, a*dw + b0);
    ((uint2*)(y + (size_t)row * D_MODEL))[threadIdx.x] = c.u;
}

// ============================================================
// fp16 HMMA GEMM: C[M,N] = A[M,K] * W[N,K]^T + bias ...
// CTA tile 128x128, BK=64, **2-stage** cp.async pipeline, 256 threads.
// 73.7 KB smem -> 2 CTAs/SM (fix for measured occ=22%).
// EPI: 0 = fp16 out (+bias), 1 = fp16 out (+bias,relu), 2 = fp32 out (+bias,+resid)
// ============================================================
constexpr int BM = 128, BN = 128, BK = 64;
constexpr int LDS = 72;
constexpr int TILE_HALVES = 128 * LDS;
constexpr int STAGE_BYTES = 2 * TILE_HALVES * 2;          // A+B = 36864
constexpr int G_STAGES = 2;
constexpr int G_SMEM = G_STAGES * STAGE_BYTES;            // 73728

template<int EPI>
__global__ void __launch_bounds__(256) gemm_h(
    const __half* __restrict__ A, const __half* __restrict__ W,
    const float* __restrict__ bias, const float* __restrict__ resid,
    float* __restrict__ Cf, __half* __restrict__ Ch, int N, int K)
{
    extern __shared__ __align__(16) char smraw[];
    __half* sm = (__half*)smraw;
    const uint32_t smb = smem_u32(sm);

    const int tid = threadIdx.x;
    const int m0 = blockIdx.y * BM, n0 = blockIdx.x * BN;
    const int KT = K >> 6;

    auto fill = [&](int kb) {
        const int st = kb & 1;
        const uint32_t sA = smb + st * STAGE_BYTES;
        const uint32_t sB = sA + TILE_HALVES * 2;
        const __half* gA = A + (size_t)m0 * K + kb * BK;
        const __half* gB = W + (size_t)n0 * K + kb * BK;
        #pragma unroll
        for (int i = 0; i < 4; i++) {
            int lin = i * 256 + tid, r = lin >> 3, c = lin & 7;
            CP_ASYNC16(sA + r * (LDS * 2) + c * 16, gA + (size_t)r * K + c * 8);
        }
        #pragma unroll
        for (int i = 0; i < 4; i++) {
            int lin = i * 256 + tid, r = lin >> 3, c = lin & 7;
            CP_ASYNC16(sB + r * (LDS * 2) + c * 16, gB + (size_t)r * K + c * 8);
        }
        CP_COMMIT();
    };

    const int warp = tid >> 5, wm = warp >> 1, wn = warp & 1;

    wmma::fragment<wmma::accumulator, 16, 16, 16, float> cf[2][4];
    #pragma unroll
    for (int i = 0; i < 2; i++)
        #pragma unroll
        for (int j = 0; j < 4; j++) wmma::fill_fragment(cf[i][j], 0.f);

    fill(0); fill(1);

    for (int kb = 0; kb < KT; kb++) {
        const int st = kb & 1;
        CP_WAIT1();
        __syncthreads();

        const __half* As = sm + st * (STAGE_BYTES / 2) + (wm * 32) * LDS;
        const __half* Bs = sm + st * (STAGE_BYTES / 2) + TILE_HALVES + (wn * 64) * LDS;

        #pragma unroll
        for (int kk = 0; kk < 4; kk++) {
            wmma::fragment<wmma::matrix_a, 16, 16, 16, __half, wmma::row_major> af[2];
            #pragma unroll
            for (int mi = 0; mi < 2; mi++)
                wmma::load_matrix_sync(af[mi], As + (mi * 16) * LDS + kk * 16, LDS);
            #pragma unroll
            for (int nj = 0; nj < 4; nj++) {
                wmma::fragment<wmma::matrix_b, 16, 16, 16, __half, wmma::col_major> bf;
                wmma::load_matrix_sync(bf, Bs + (nj * 16) * LDS + kk * 16, LDS);
                #pragma unroll
                for (int mi = 0; mi < 2; mi++)
                    wmma::mma_sync(cf[mi][nj], af[mi], bf, cf[mi][nj]);
            }
        }
        __syncthreads();
        if (kb + G_STAGES < KT) fill(kb + G_STAGES); else CP_COMMIT();
    }

    // epilogue: stage accum to smem (reuse pipeline smem), then fused store
    float* Cs = (float*)sm;                    // 128 x 136 floats = 69632 B < 73728
    constexpr int LDC = 136;
    #pragma unroll
    for (int mi = 0; mi < 2; mi++)
        #pragma unroll
        for (int nj = 0; nj < 4; nj++)
            wmma::store_matrix_sync(Cs + (wm*32 + mi*16) * LDC + wn*64 + nj*16,
                                    cf[mi][nj], LDC, wmma::mem_row_major);
    __syncthreads();

    #pragma unroll
    for (int i = 0; i < 16; i++) {
        int lin = i * 256 + tid, r = lin >> 5, c4 = lin & 31;
        float4 v = *(float4*)(Cs + r * LDC + c4 * 4);
        float4 bv = *(const float4*)(bias + n0 + c4 * 4);
        v.x += bv.x; v.y += bv.y; v.z += bv.z; v.w += bv.w;
        if (EPI == 1) {
            v.x = fmaxf(v.x, 0.f); v.y = fmaxf(v.y, 0.f);
            v.z = fmaxf(v.z, 0.f); v.w = fmaxf(v.w, 0.f);
        }
        if (EPI == 2) {
            float4 rv = *(const float4*)(resid + (size_t)(m0 + r) * N + n0 + c4 * 4);
            v.x += rv.x; v.y += rv.y; v.z += rv.z; v.w += rv.w;
            *(float4*)(Cf + (size_t)(m0 + r) * N + n0 + c4 * 4) = v;
        } else {
            union { __half2 h[2]; uint2 u; } stv;
            stv.h[0] = __floats2half2_rn(v.x, v.y);
            stv.h[1] = __floats2half2_rn(v.z, v.w);
            *(uint2*)(Ch + (size_t)(m0 + r) * N + n0 + c4 * 4) = stv.u;
        }
    }
}

// ============================================================
// Flash attention (round-8 version: synchronous K/V loads, 72.2 KB,
// 3 CTAs/SM — measured faster than the double-buffered variant).
// grid = (SEQ/64, BATCH*N_HEADS), 128 threads (4 warps).
// ============================================================
constexpr int LDH = 72;   // half row stride
constexpr int LDF = 68;   // float row stride
constexpr int ATTN_SMEM = 4 * 64 * LDH * 2 + 2 * 64 * LDF * 4 + 2 * 64 * 4; // 72192

__global__ void __launch_bounds__(128) attn_kernel(
    const __half* __restrict__ Q, const __half* __restrict__ K,
    const __half* __restrict__ V, __half* __restrict__ O)
{
    extern __shared__ __align__(16) char sm[];
    __half* Qs = (__half*)(sm);
    __half* Ks = Qs + 64 * LDH;
    __half* Vs = Ks + 64 * LDH;
    __half* Ps = Vs + 64 * LDH;
    float*  Ss = (float*)(Ps + 64 * LDH);
    float*  Os = Ss + 64 * LDF;
    float*  Ml = Os + 64 * LDF;
    float*  Ll = Ml + 64;

    const int tid = threadIdx.x;
    const int b = blockIdx.y >> 4, h = blockIdx.y & 15;
    const size_t base = (size_t)b * SEQ * D_MODEL + (size_t)h * 64;
    const int q0 = blockIdx.x * 64;
    const __half2 qs2 = __floats2half2_rn(0.125f, 0.125f);

    // load Q (scaled by exact 1/8), init O/m/l
    #pragma unroll
    for (int i = 0; i < 4; i++) {
        int lin = i * 128 + tid, r = lin >> 3, c = lin & 7;
        union { __half2 h[4]; uint4 u; } v;
        v.u = *(const uint4*)(Q + base + (size_t)(q0 + r) * D_MODEL + c * 8);
        #pragma unroll
        for (int t = 0; t < 4; t++) v.h[t] = __hmul2(v.h[t], qs2);
        *(uint4*)(Qs + r * LDH + c * 8) = v.u;
    }
    #pragma unroll
    for (int i = 0; i < 8; i++) {
        int lin = i * 128 + tid, r = lin >> 4, c4 = lin & 15;
        *(float4*)(Os + r * LDF + c4 * 4) = make_float4(0.f, 0.f, 0.f, 0.f);
    }
    if (tid < 64) { Ml[tid] = -1e30f; Ll[tid] = 0.f; }
    __syncthreads();

    const int w = tid >> 5;

    for (int kt = 0; kt < SEQ / 64; kt++) {
        const int k0 = kt * 64;
        #pragma unroll
        for (int i = 0; i < 4; i++) {
            int lin = i * 128 + tid, r = lin >> 3, c = lin & 7;
            *(uint4*)(Ks + r * LDH + c * 8) =
                *(const uint4*)(K + base + (size_t)(k0 + r) * D_MODEL + c * 8);
            *(uint4*)(Vs + r * LDH + c * 8) =
                *(const uint4*)(V + base + (size_t)(k0 + r) * D_MODEL + c * 8);
        }
        __syncthreads();

        // S = Qs * Ks^T  (warp: 16 q-rows x 64 keys)
        {
            wmma::fragment<wmma::accumulator, 16, 16, 16, float> sf[4];
            #pragma unroll
            for (int nj = 0; nj < 4; nj++) wmma::fill_fragment(sf[nj], 0.f);
            #pragma unroll
            for (int kk = 0; kk < 4; kk++) {
                wmma::fragment<wmma::matrix_a, 16, 16, 16, __half, wmma::row_major> af;
                wmma::load_matrix_sync(af, Qs + (w * 16) * LDH + kk * 16, LDH);
                #pragma unroll
                for (int nj = 0; nj < 4; nj++) {
                    wmma::fragment<wmma::matrix_b, 16, 16, 16, __half, wmma::col_major> bf;
                    wmma::load_matrix_sync(bf, Ks + (nj * 16) * LDH + kk * 16, LDH);
                    wmma::mma_sync(sf[nj], af, bf, sf[nj]);
                }
            }
            #pragma unroll
            for (int nj = 0; nj < 4; nj++)
                wmma::store_matrix_sync(Ss + (w * 16) * LDF + nj * 16, sf[nj], LDF,
                                        wmma::mem_row_major);
        }
        __syncthreads();

        // online softmax: 2 threads/row, write P in fp16
        {
            const int row = tid >> 1, hh = tid & 1;
            float* sr = Ss + row * LDF + hh * 32;
            __half* pr = Ps + row * LDH + hh * 32;
            float mx = -1e30f;
            #pragma unroll 8
            for (int c = 0; c < 32; c++) mx = fmaxf(mx, sr[c]);
            mx = fmaxf(mx, __shfl_xor_sync(0xffffffffu, mx, 1));
            const float mold = Ml[row];
            const float mnew = fmaxf(mold, mx);
            const float fac = __expf(mold - mnew);
            float ssum = 0.f;
            #pragma unroll 8
            for (int c = 0; c < 32; c++) {
                float e = __expf(sr[c] - mnew);
                pr[c] = __float2half(e);
                ssum += e;
            }
            ssum += __shfl_xor_sync(0xffffffffu, ssum, 1);
            float* orow = Os + row * LDF + hh * 32;
            #pragma unroll 8
            for (int c = 0; c < 32; c++) orow[c] *= fac;
            if (hh == 0) { Ml[row] = mnew; Ll[row] = Ll[row] * fac + ssum; }
        }
        __syncthreads();

        // O += P * V
        {
            #pragma unroll
            for (int nj = 0; nj < 4; nj++) {
                wmma::fragment<wmma::accumulator, 16, 16, 16, float> of;
                wmma::load_matrix_sync(of, Os + (w * 16) * LDF + nj * 16, LDF,
                                       wmma::mem_row_major);
                #pragma unroll
                for (int kk = 0; kk < 4; kk++) {
                    wmma::fragment<wmma::matrix_a, 16, 16, 16, __half, wmma::row_major> af;
                    wmma::load_matrix_sync(af, Ps + (w * 16) * LDH + kk * 16, LDH);
                    wmma::fragment<wmma::matrix_b, 16, 16, 16, __half, wmma::row_major> bf;
                    wmma::load_matrix_sync(bf, Vs + (kk * 16) * LDH + nj * 16, LDH);
                    wmma::mma_sync(of, af, bf, of);
                }
                wmma::store_matrix_sync(Os + (w * 16) * LDF + nj * 16, of, LDF,
                                        wmma::mem_row_major);
            }
        }
        __syncthreads();
    }

    // normalize + store fp16
    {
        const int row = tid >> 1, hh = tid & 1;
        const float inv = 1.f / Ll[row];
        #pragma unroll
        for (int c4 = 0; c4 < 8; c4++) {
            float4 v = *(float4*)(Os + row * LDF + hh * 32 + c4 * 4);
            union { __half2 h[2]; uint2 u; } st;
            st.h[0] = __floats2half2_rn(v.x * inv, v.y * inv);
            st.h[1] = __floats2half2_rn(v.z * inv, v.w * inv);
            *(uint2*)(O + base + (size_t)(q0 + row) * D_MODEL + hh * 32 + c4 * 4) = st.u;
        }
    }
}

// ============================================================
// launcher
// ============================================================
extern "C" void kernel_launch(void* const* d_in, const int* in_sizes, int n_in,
                              void* d_out, int out_size)
{
    const float* x    = (const float*)d_in[0];
    const float* wq   = (const float*)d_in[2];
    const float* bq   = (const float*)d_in[3];
    const float* wk   = (const float*)d_in[4];
    const float* bk   = (const float*)d_in[5];
    const float* wv   = (const float*)d_in[6];
    const float* bv   = (const float*)d_in[7];
    const float* wo   = (const float*)d_in[8];
    const float* bo   = (const float*)d_in[9];
    const float* w1   = (const float*)d_in[10];
    const float* b1   = (const float*)d_in[11];
    const float* w2   = (const float*)d_in[12];
    const float* b2   = (const float*)d_in[13];
    const float* ln1a = (const float*)d_in[14];
    const float* ln1b = (const float*)d_in[15];
    const float* ln2a = (const float*)d_in[16];
    const float* ln2b = (const float*)d_in[17];
    float* out = (float*)d_out;

    void* p;
    cudaGetSymbolAddress(&p, g_h);   __half* h   = (__half*)p;
    cudaGetSymbolAddress(&p, g_q);   __half* q   = (__half*)p;
    cudaGetSymbolAddress(&p, g_k);   __half* k   = (__half*)p;
    cudaGetSymbolAddress(&p, g_v);   __half* v   = (__half*)p;
    cudaGetSymbolAddress(&p, g_ctx); __half* ctx = (__half*)p;
    cudaGetSymbolAddress(&p, g_f1);  __half* f1  = (__half*)p;
    cudaGetSymbolAddress(&p, g_x1);  float*  x1  = (float*)p;

    cudaFuncSetAttribute(gemm_h<0>, cudaFuncAttributeMaxDynamicSharedMemorySize, G_SMEM);
    cudaFuncSetAttribute(gemm_h<1>, cudaFuncAttributeMaxDynamicSharedMemorySize, G_SMEM);
    cudaFuncSetAttribute(gemm_h<2>, cudaFuncAttributeMaxDynamicSharedMemorySize, G_SMEM);
    cudaFuncSetAttribute(attn_kernel, cudaFuncAttributeMaxDynamicSharedMemorySize, ATTN_SMEM);

    __half* wqh; __half* wkh; __half* wvh; __half* woh; __half* w1h; __half* w2h;
    cudaGetSymbolAddress(&p, g_wq); wqh = (__half*)p;
    cudaGetSymbolAddress(&p, g_wk); wkh = (__half*)p;
    cudaGetSymbolAddress(&p, g_wv); wvh = (__half*)p;
    cudaGetSymbolAddress(&p, g_wo); woh = (__half*)p;
    cudaGetSymbolAddress(&p, g_w1); w1h = (__half*)p;
    cudaGetSymbolAddress(&p, g_w2); w2h = (__half*)p;

    // all weights -> fp16 (single launch)
    f2h_all_kernel<<<NW_TOT / 1024, 256>>>(wq, wk, wv, wo, w1, w2);

    // LN1 -> h (fp16)
    ln_kernel<<<TOK, 256>>>(x, ln1a, ln1b, h);

    // QKV projections (fp16 out)
    dim3 g1024(D_MODEL / 128, TOK / 128);
    gemm_h<0><<<g1024, 256, G_SMEM>>>(h, wqh, bq, nullptr, nullptr, q, D_MODEL, D_MODEL);
    gemm_h<0><<<g1024, 256, G_SMEM>>>(h, wkh, bk, nullptr, nullptr, k, D_MODEL, D_MODEL);
    gemm_h<0><<<g1024, 256, G_SMEM>>>(h, wvh, bv, nullptr, nullptr, v, D_MODEL, D_MODEL);

    // attention -> ctx (fp16)
    attn_kernel<<<dim3(SEQ / 64, BATCH * N_HEADS), 128, ATTN_SMEM>>>(q, k, v, ctx);

    // W_O + residual -> x1 (fp32)
    gemm_h<2><<<g1024, 256, G_SMEM>>>(ctx, woh, bo, x, x1, nullptr, D_MODEL, D_MODEL);

    // LN2 -> h (fp16)
    ln_kernel<<<TOK, 256>>>(x1, ln2a, ln2b, h);

    // FFN
    gemm_h<1><<<dim3(D_FF / 128, TOK / 128), 256, G_SMEM>>>(h, w1h, b1, nullptr, nullptr, f1, D_FF, D_MODEL);
    gemm_h<2><<<g1024, 256, G_SMEM>>>(f1, w2h, b2, x1, out, nullptr, D_MODEL, D_FF);
}

// round 13
// speedup vs baseline: 1.1679x; 1.1565x over previous
#include <cuda_runtime.h>
#include <cuda_fp16.h>
#include <mma.h>
#include <cstdint>

using namespace nvcuda;

// ---------------- problem constants ----------------
constexpr int D_MODEL = 1024;
constexpr int N_HEADS = 16;
constexpr int D_FF    = 4096;
constexpr int BATCH   = 4;
constexpr int SEQ     = 2048;
constexpr int TOK     = BATCH * SEQ;   // 8192

// ---------------- scratch (device globals; no allocation allowed) ----------------
__device__ __half g_h  [(size_t)TOK * D_MODEL];
__device__ __half g_q  [(size_t)TOK * D_MODEL];
__device__ __half g_k  [(size_t)TOK * D_MODEL];
__device__ __half g_v  [(size_t)TOK * D_MODEL];
__device__ __half g_ctx[(size_t)TOK * D_MODEL];
__device__ __half g_f1 [(size_t)TOK * D_FF];
__device__ float  g_x1 [(size_t)TOK * D_MODEL];
__device__ __half g_wq [(size_t)D_MODEL * D_MODEL];
__device__ __half g_wk [(size_t)D_MODEL * D_MODEL];
__device__ __half g_wv [(size_t)D_MODEL * D_MODEL];
__device__ __half g_wo [(size_t)D_MODEL * D_MODEL];
__device__ __half g_w1 [(size_t)D_FF * D_MODEL];
__device__ __half g_w2 [(size_t)D_MODEL * D_FF];

// ================= cp.async =================
#define CP_ASYNC16(dst, src) \
    asm volatile("cp.async.cg.shared.global [%0], [%1], 16;" :: "r"(dst), "l"(src))
#define CP_COMMIT() asm volatile("cp.async.commit_group;")
#define CP_WAIT2()  asm volatile("cp.async.wait_group 2;")

__device__ __forceinline__ uint32_t smem_u32(const void* p) {
    uint32_t a;
    asm("{ .reg .u64 t; cvta.to.shared.u64 t, %1; cvt.u32.u64 %0, t; }" : "=r"(a) : "l"(p));
    return a;
}

// ============================================================
// fused weight fp32 -> fp16 conversion (single launch, all 6 weights)
// ============================================================
constexpr int NW1 = D_MODEL * D_MODEL;       // 1048576
constexpr int NW2 = D_FF * D_MODEL;          // 4194304
constexpr int NW_TOT = 4 * NW1 + 2 * NW2;    // 12582912

__global__ void __launch_bounds__(256) f2h_all_kernel(
    const float* __restrict__ wq, const float* __restrict__ wk,
    const float* __restrict__ wv, const float* __restrict__ wo,
    const float* __restrict__ w1, const float* __restrict__ w2)
{
    int e = (blockIdx.x * 256 + threadIdx.x) * 4;
    if (e >= NW_TOT) return;
    const float* s;
    __half* d;
    int off;
    if (e < 4 * NW1) {
        int seg = e >> 20;                    // NW1 = 1<<20
        off = e & (NW1 - 1);
        switch (seg) {
            case 0:  s = wq; break;
            case 1:  s = wk; break;
            case 2:  s = wv; break;
            default: s = wo; break;
        }
        __half* dst[4] = {g_wq, g_wk, g_wv, g_wo};
        d = dst[seg];
    } else if (e < 4 * NW1 + NW2) {
        s = w1; d = g_w1; off = e - 4 * NW1;
    } else {
        s = w2; d = g_w2; off = e - 4 * NW1 - NW2;
    }
    float4 v = *(const float4*)(s + off);
    union { __half2 h[2]; uint2 u; } c;
    c.h[0] = __floats2half2_rn(v.x, v.y);
    c.h[1] = __floats2half2_rn(v.z, v.w);
    *(uint2*)(d + off) = c.u;
}

// ============================================================
// LayerNorm (torch semantics: ddof=1, /(std+eps)) fp32 in -> fp16 out
// ============================================================
__global__ void __launch_bounds__(256) ln_kernel(
    const float* __restrict__ x, const float* __restrict__ ga,
    const float* __restrict__ gb, __half* __restrict__ y)
{
    int row = blockIdx.x;
    const float4 v = ((const float4*)(x + (size_t)row * D_MODEL))[threadIdx.x];

    __shared__ float red[32];
    int lane = threadIdx.x & 31, wid = threadIdx.x >> 5;

    float s = v.x + v.y + v.z + v.w;
    #pragma unroll
    for (int o = 16; o; o >>= 1) s += __shfl_down_sync(0xffffffffu, s, o);
    if (lane == 0) red[wid] = s;
    __syncthreads();
    if (wid == 0) {
        float t = (lane < 8) ? red[lane] : 0.f;
        #pragma unroll
        for (int o = 4; o; o >>= 1) t += __shfl_down_sync(0xffffffffu, t, o);
        if (lane == 0) red[0] = t;
    }
    __syncthreads();
    float mean = red[0] * (1.f / 1024.f);

    float dx = v.x - mean, dy = v.y - mean, dz = v.z - mean, dw = v.w - mean;
    float s2 = dx*dx + dy*dy + dz*dz + dw*dw;
    #pragma unroll
    for (int o = 16; o; o >>= 1) s2 += __shfl_down_sync(0xffffffffu, s2, o);
    __syncthreads();
    if (lane == 0) red[wid] = s2;
    __syncthreads();
    if (wid == 0) {
        float t = (lane < 8) ? red[lane] : 0.f;
        #pragma unroll
        for (int o = 4; o; o >>= 1) t += __shfl_down_sync(0xffffffffu, t, o);
        if (lane == 0) red[0] = t;
    }
    __syncthreads();
    float var = red[0] * (1.f / 1023.f);
    float inv = 1.f / (sqrtf(var) + 1e-5f);
    float a = ga[0] * inv, b0 = gb[0];

    union { __half2 h[2]; uint2 u; } c;
    c.h[0] = __floats2half2_rn(a*dx + b0, a*dy + b0);
    c.h[1] = __floats2half2_rn(a*dz + b0, a*dw + b0);
    ((uint2*)(y + (size_t)row * D_MODEL))[threadIdx.x] = c.u;
}

// ============================================================
// fp16 HMMA GEMM: CTA tile 128x128, BK=64, 3-stage cp.async pipeline.
// __launch_bounds__(256,2) pins regs<=128 so 2 CTAs/SM (measured-good config).
// EPI: 0 = fp16 out (+bias), 1 = fp16 out (+bias,relu), 2 = fp32 out (+bias,+resid)
// ============================================================
constexpr int BM = 128, BN = 128, BK = 64;
constexpr int LDS = 72;
constexpr int TILE_HALVES = 128 * LDS;
constexpr int STAGE_BYTES = 2 * TILE_HALVES * 2;          // A+B = 36864
constexpr int G_STAGES = 3;
constexpr int G_SMEM = G_STAGES * STAGE_BYTES;            // 110592

template<int EPI>
__global__ void __launch_bounds__(256, 2) gemm_h(
    const __half* __restrict__ A, const __half* __restrict__ W,
    const float* __restrict__ bias, const float* __restrict__ resid,
    float* __restrict__ Cf, __half* __restrict__ Ch, int N, int K)
{
    extern __shared__ __align__(16) char smraw[];
    __half* sm = (__half*)smraw;
    const uint32_t smb = smem_u32(sm);

    const int tid = threadIdx.x;
    const int m0 = blockIdx.y * BM, n0 = blockIdx.x * BN;
    const int KT = K >> 6;

    auto fill = [&](int kb) {
        const int st = kb % G_STAGES;
        const uint32_t sA = smb + st * STAGE_BYTES;
        const uint32_t sB = sA + TILE_HALVES * 2;
        const __half* gA = A + (size_t)m0 * K + kb * BK;
        const __half* gB = W + (size_t)n0 * K + kb * BK;
        #pragma unroll
        for (int i = 0; i < 4; i++) {
            int lin = i * 256 + tid, r = lin >> 3, c = lin & 7;
            CP_ASYNC16(sA + r * (LDS * 2) + c * 16, gA + (size_t)r * K + c * 8);
        }
        #pragma unroll
        for (int i = 0; i < 4; i++) {
            int lin = i * 256 + tid, r = lin >> 3, c = lin & 7;
            CP_ASYNC16(sB + r * (LDS * 2) + c * 16, gB + (size_t)r * K + c * 8);
        }
        CP_COMMIT();
    };

    const int warp = tid >> 5, wm = warp >> 1, wn = warp & 1;

    wmma::fragment<wmma::accumulator, 16, 16, 16, float> cf[2][4];
    #pragma unroll
    for (int i = 0; i < 2; i++)
        #pragma unroll
        for (int j = 0; j < 4; j++) wmma::fill_fragment(cf[i][j], 0.f);

    fill(0); fill(1); fill(2);

    for (int kb = 0; kb < KT; kb++) {
        const int st = kb % G_STAGES;
        CP_WAIT2();
        __syncthreads();

        const __half* As = sm + st * (STAGE_BYTES / 2) + (wm * 32) * LDS;
        const __half* Bs = sm + st * (STAGE_BYTES / 2) + TILE_HALVES + (wn * 64) * LDS;

        #pragma unroll
        for (int kk = 0; kk < 4; kk++) {
            wmma::fragment<wmma::matrix_a, 16, 16, 16, __half, wmma::row_major> af[2];
            #pragma unroll
            for (int mi = 0; mi < 2; mi++)
                wmma::load_matrix_sync(af[mi], As + (mi * 16) * LDS + kk * 16, LDS);
            #pragma unroll
            for (int nj = 0; nj < 4; nj++) {
                wmma::fragment<wmma::matrix_b, 16, 16, 16, __half, wmma::col_major> bf;
                wmma::load_matrix_sync(bf, Bs + (nj * 16) * LDS + kk * 16, LDS);
                #pragma unroll
                for (int mi = 0; mi < 2; mi++)
                    wmma::mma_sync(cf[mi][nj], af[mi], bf, cf[mi][nj]);
            }
        }
        __syncthreads();
        if (kb + G_STAGES < KT) fill(kb + G_STAGES); else CP_COMMIT();
    }

    // epilogue: stage accum to smem (reuse pipeline smem), then fused store
    float* Cs = (float*)sm;                    // 128 x 136 floats = 69632 B
    constexpr int LDC = 136;
    #pragma unroll
    for (int mi = 0; mi < 2; mi++)
        #pragma unroll
        for (int nj = 0; nj < 4; nj++)
            wmma::store_matrix_sync(Cs + (wm*32 + mi*16) * LDC + wn*64 + nj*16,
                                    cf[mi][nj], LDC, wmma::mem_row_major);
    __syncthreads();

    #pragma unroll
    for (int i = 0; i < 16; i++) {
        int lin = i * 256 + tid, r = lin >> 5, c4 = lin & 31;
        float4 v = *(float4*)(Cs + r * LDC + c4 * 4);
        float4 bv = *(const float4*)(bias + n0 + c4 * 4);
        v.x += bv.x; v.y += bv.y; v.z += bv.z; v.w += bv.w;
        if (EPI == 1) {
            v.x = fmaxf(v.x, 0.f); v.y = fmaxf(v.y, 0.f);
            v.z = fmaxf(v.z, 0.f); v.w = fmaxf(v.w, 0.f);
        }
        if (EPI == 2) {
            float4 rv = *(const float4*)(resid + (size_t)(m0 + r) * N + n0 + c4 * 4);
            v.x += rv.x; v.y += rv.y; v.z += rv.z; v.w += rv.w;
            *(float4*)(Cf + (size_t)(m0 + r) * N + n0 + c4 * 4) = v;
        } else {
            union { __half2 h[2]; uint2 u; } stv;
            stv.h[0] = __floats2half2_rn(v.x, v.y);
            stv.h[1] = __floats2half2_rn(v.z, v.w);
            *(uint2*)(Ch + (size_t)(m0 + r) * N + n0 + c4 * 4) = stv.u;
        }
    }
}

// ============================================================
// Flash attention, warp-local softmax (2 syncs/iter instead of 4).
// Warp w owns q-rows [16w,16w+16) for S, softmax, and P*V.
// m/l live in registers (2 lanes per row, shfl-paired).
// grid = (SEQ/64, BATCH*N_HEADS), 128 threads (4 warps), 71.7KB smem -> 3 CTAs/SM.
// ============================================================
constexpr int LDH = 72;   // half row stride (144 B = 9*16)
constexpr int LDF = 68;   // float row stride (272 B = 17*16)
constexpr int ATTN_SMEM = 4 * 64 * LDH * 2 + 2 * 64 * LDF * 4;  // 36864+34816 = 71680

__global__ void __launch_bounds__(128) attn_kernel(
    const __half* __restrict__ Q, const __half* __restrict__ K,
    const __half* __restrict__ V, __half* __restrict__ O)
{
    extern __shared__ __align__(16) char sm[];
    __half* Qs = (__half*)(sm);
    __half* Ks = Qs + 64 * LDH;
    __half* Vs = Ks + 64 * LDH;
    __half* Ps = Vs + 64 * LDH;
    float*  Ss = (float*)(Ps + 64 * LDH);
    float*  Os = Ss + 64 * LDF;

    const int tid = threadIdx.x;
    const int w = tid >> 5, lane = tid & 31;
    const int b = blockIdx.y >> 4, h = blockIdx.y & 15;
    const size_t base = (size_t)b * SEQ * D_MODEL + (size_t)h * 64;
    const int q0 = blockIdx.x * 64;
    const __half2 qs2 = __floats2half2_rn(0.125f, 0.125f);

    // this lane's softmax row (warp-local): 2 lanes per row, 32 cols each
    const int srow = w * 16 + (lane >> 1);   // 0..63
    const int hh = lane & 1;

    // load Q (scaled by exact 1/8), init O
    #pragma unroll
    for (int i = 0; i < 4; i++) {
        int lin = i * 128 + tid, r = lin >> 3, c = lin & 7;
        union { __half2 h[4]; uint4 u; } v;
        v.u = *(const uint4*)(Q + base + (size_t)(q0 + r) * D_MODEL + c * 8);
        #pragma unroll
        for (int t = 0; t < 4; t++) v.h[t] = __hmul2(v.h[t], qs2);
        *(uint4*)(Qs + r * LDH + c * 8) = v.u;
    }
    #pragma unroll
    for (int i = 0; i < 8; i++) {
        int lin = i * 128 + tid, r = lin >> 4, c4 = lin & 15;
        *(float4*)(Os + r * LDF + c4 * 4) = make_float4(0.f, 0.f, 0.f, 0.f);
    }

    float m_reg = -1e30f, l_reg = 0.f;

    for (int kt = 0; kt < SEQ / 64; kt++) {
        const int k0 = kt * 64;
        __syncthreads();   // all warps done with previous Ks/Vs
        #pragma unroll
        for (int i = 0; i < 4; i++) {
            int lin = i * 128 + tid, r = lin >> 3, c = lin & 7;
            *(uint4*)(Ks + r * LDH + c * 8) =
                *(const uint4*)(K + base + (size_t)(k0 + r) * D_MODEL + c * 8);
            *(uint4*)(Vs + r * LDH + c * 8) =
                *(const uint4*)(V + base + (size_t)(k0 + r) * D_MODEL + c * 8);
        }
        __syncthreads();

        // S = Qs * Ks^T  (warp w: rows [16w,16w+16) x 64 keys)
        {
            wmma::fragment<wmma::accumulator, 16, 16, 16, float> sf[4];
            #pragma unroll
            for (int nj = 0; nj < 4; nj++) wmma::fill_fragment(sf[nj], 0.f);
            #pragma unroll
            for (int kk = 0; kk < 4; kk++) {
                wmma::fragment<wmma::matrix_a, 16, 16, 16, __half, wmma::row_major> af;
                wmma::load_matrix_sync(af, Qs + (w * 16) * LDH + kk * 16, LDH);
                #pragma unroll
                for (int nj = 0; nj < 4; nj++) {
                    wmma::fragment<wmma::matrix_b, 16, 16, 16, __half, wmma::col_major> bf;
                    wmma::load_matrix_sync(bf, Ks + (nj * 16) * LDH + kk * 16, LDH);
                    wmma::mma_sync(sf[nj], af, bf, sf[nj]);
                }
            }
            #pragma unroll
            for (int nj = 0; nj < 4; nj++)
                wmma::store_matrix_sync(Ss + (w * 16) * LDF + nj * 16, sf[nj], LDF,
                                        wmma::mem_row_major);
        }
        // NO syncthreads: softmax rows belong to this warp

        // warp-local online softmax (vectorized), m/l in registers
        {
            const float4* sr4 = (const float4*)(Ss + srow * LDF + hh * 32);
            float mx = -1e30f;
            #pragma unroll
            for (int j = 0; j < 8; j++) {
                float4 v = sr4[j];
                mx = fmaxf(mx, fmaxf(fmaxf(v.x, v.y), fmaxf(v.z, v.w)));
            }
            mx = fmaxf(mx, __shfl_xor_sync(0xffffffffu, mx, 1));
            const float mnew = fmaxf(m_reg, mx);
            const float fac = __expf(m_reg - mnew);
            float ssum = 0.f;
            uint2* pr = (uint2*)(Ps + srow * LDH + hh * 32);
            #pragma unroll
            for (int j = 0; j < 8; j++) {
                float4 v = sr4[j];
                float e0 = __expf(v.x - mnew), e1 = __expf(v.y - mnew);
                float e2 = __expf(v.z - mnew), e3 = __expf(v.w - mnew);
                ssum += (e0 + e1) + (e2 + e3);
                union { __half2 h[2]; uint2 u; } pk;
                pk.h[0] = __floats2half2_rn(e0, e1);
                pk.h[1] = __floats2half2_rn(e2, e3);
                pr[j] = pk.u;
            }
            ssum += __shfl_xor_sync(0xffffffffu, ssum, 1);
            l_reg = l_reg * fac + ssum;
            m_reg = mnew;
            float4* orow = (float4*)(Os + srow * LDF + hh * 32);
            #pragma unroll
            for (int j = 0; j < 8; j++) {
                float4 v = orow[j];
                v.x *= fac; v.y *= fac; v.z *= fac; v.w *= fac;
                orow[j] = v;
            }
        }
        // NO syncthreads: P rows and O rows belong to this warp

        // O += P * V  (warp w: its own 16 rows)
        {
            #pragma unroll
            for (int nj = 0; nj < 4; nj++) {
                wmma::fragment<wmma::accumulator, 16, 16, 16, float> of;
                wmma::load_matrix_sync(of, Os + (w * 16) * LDF + nj * 16, LDF,
                                       wmma::mem_row_major);
                #pragma unroll
                for (int kk = 0; kk < 4; kk++) {
                    wmma::fragment<wmma::matrix_a, 16, 16, 16, __half, wmma::row_major> af;
                    wmma::load_matrix_sync(af, Ps + (w * 16) * LDH + kk * 16, LDH);
                    wmma::fragment<wmma::matrix_b, 16, 16, 16, __half, wmma::row_major> bf;
                    wmma::load_matrix_sync(bf, Vs + (kk * 16) * LDH + nj * 16, LDH);
                    wmma::mma_sync(of, af, bf, of);
                }
                wmma::store_matrix_sync(Os + (w * 16) * LDF + nj * 16, of, LDF,
                                        wmma::mem_row_major);
            }
        }
    }

    // normalize + store fp16 (warp-local rows; l in register)
    {
        const float inv = 1.f / l_reg;
        const float4* orow = (const float4*)(Os + srow * LDF + hh * 32);
        #pragma unroll
        for (int c4 = 0; c4 < 8; c4++) {
            float4 v = orow[c4];
            union { __half2 h[2]; uint2 u; } st;
            st.h[0] = __floats2half2_rn(v.x * inv, v.y * inv);
            st.h[1] = __floats2half2_rn(v.z * inv, v.w * inv);
            *(uint2*)(O + base + (size_t)(q0 + srow) * D_MODEL + hh * 32 + c4 * 4) = st.u;
        }
    }
}

// ============================================================
// launcher
// ============================================================
extern "C" void kernel_launch(void* const* d_in, const int* in_sizes, int n_in,
                              void* d_out, int out_size)
{
    const float* x    = (const float*)d_in[0];
    const float* wq   = (const float*)d_in[2];
    const float* bq   = (const float*)d_in[3];
    const float* wk   = (const float*)d_in[4];
    const float* bk   = (const float*)d_in[5];
    const float* wv   = (const float*)d_in[6];
    const float* bv   = (const float*)d_in[7];
    const float* wo   = (const float*)d_in[8];
    const float* bo   = (const float*)d_in[9];
    const float* w1   = (const float*)d_in[10];
    const float* b1   = (const float*)d_in[11];
    const float* w2   = (const float*)d_in[12];
    const float* b2   = (const float*)d_in[13];
    const float* ln1a = (const float*)d_in[14];
    const float* ln1b = (const float*)d_in[15];
    const float* ln2a = (const float*)d_in[16];
    const float* ln2b = (const float*)d_in[17];
    float* out = (float*)d_out;

    void* p;
    cudaGetSymbolAddress(&p, g_h);   __half* h   = (__half*)p;
    cudaGetSymbolAddress(&p, g_q);   __half* q   = (__half*)p;
    cudaGetSymbolAddress(&p, g_k);   __half* k   = (__half*)p;
    cudaGetSymbolAddress(&p, g_v);   __half* v   = (__half*)p;
    cudaGetSymbolAddress(&p, g_ctx); __half* ctx = (__half*)p;
    cudaGetSymbolAddress(&p, g_f1);  __half* f1  = (__half*)p;
    cudaGetSymbolAddress(&p, g_x1);  float*  x1  = (float*)p;

    cudaFuncSetAttribute(gemm_h<0>, cudaFuncAttributeMaxDynamicSharedMemorySize, G_SMEM);
    cudaFuncSetAttribute(gemm_h<1>, cudaFuncAttributeMaxDynamicSharedMemorySize, G_SMEM);
    cudaFuncSetAttribute(gemm_h<2>, cudaFuncAttributeMaxDynamicSharedMemorySize, G_SMEM);
    cudaFuncSetAttribute(attn_kernel, cudaFuncAttributeMaxDynamicSharedMemorySize, ATTN_SMEM);

    __half* wqh; __half* wkh; __half* wvh; __half* woh; __half* w1h; __half* w2h;
    cudaGetSymbolAddress(&p, g_wq); wqh = (__half*)p;
    cudaGetSymbolAddress(&p, g_wk); wkh = (__half*)p;
    cudaGetSymbolAddress(&p, g_wv); wvh = (__half*)p;
    cudaGetSymbolAddress(&p, g_wo); woh = (__half*)p;
    cudaGetSymbolAddress(&p, g_w1); w1h = (__half*)p;
    cudaGetSymbolAddress(&p, g_w2); w2h = (__half*)p;

    // all weights -> fp16 (single launch)
    f2h_all_kernel<<<NW_TOT / 1024, 256>>>(wq, wk, wv, wo, w1, w2);

    // LN1 -> h (fp16)
    ln_kernel<<<TOK, 256>>>(x, ln1a, ln1b, h);

    // QKV projections (fp16 out)
    dim3 g1024(D_MODEL / 128, TOK / 128);
    gemm_h<0><<<g1024, 256, G_SMEM>>>(h, wqh, bq, nullptr, nullptr, q, D_MODEL, D_MODEL);
    gemm_h<0><<<g1024, 256, G_SMEM>>>(h, wkh, bk, nullptr, nullptr, k, D_MODEL, D_MODEL);
    gemm_h<0><<<g1024, 256, G_SMEM>>>(h, wvh, bv, nullptr, nullptr, v, D_MODEL, D_MODEL);

    // attention -> ctx (fp16)
    attn_kernel<<<dim3(SEQ / 64, BATCH * N_HEADS), 128, ATTN_SMEM>>>(q, k, v, ctx);

    // W_O + residual -> x1 (fp32)
    gemm_h<2><<<g1024, 256, G_SMEM>>>(ctx, woh, bo, x, x1, nullptr, D_MODEL, D_MODEL);

    // LN2 -> h (fp16)
    ln_kernel<<<TOK, 256>>>(x1, ln2a, ln2b, h);

    // FFN
    gemm_h<1><<<dim3(D_FF / 128, TOK / 128), 256, G_SMEM>>>(h, w1h, b1, nullptr, nullptr, f1, D_FF, D_MODEL);
    gemm_h<2><<<g1024, 256, G_SMEM>>>(f1, w2h, b2, x1, out, nullptr, D_MODEL, D_FF);
}

// round 17
// speedup vs baseline: 1.4651x; 1.2544x over previous
#include <cuda_runtime.h>
#include <cuda_fp16.h>
#include <mma.h>
#include <cstdint>

using namespace nvcuda;

// ---------------- problem constants ----------------
constexpr int D_MODEL = 1024;
constexpr int N_HEADS = 16;
constexpr int D_FF    = 4096;
constexpr int BATCH   = 4;
constexpr int SEQ     = 2048;
constexpr int TOK     = BATCH * SEQ;   // 8192

// ---------------- scratch (device globals; no allocation allowed) ----------------
__device__ __half g_h  [(size_t)TOK * D_MODEL];
__device__ __half g_q  [(size_t)TOK * D_MODEL];
__device__ __half g_k  [(size_t)TOK * D_MODEL];
__device__ __half g_v  [(size_t)TOK * D_MODEL];
__device__ __half g_ctx[(size_t)TOK * D_MODEL];
__device__ __half g_f1 [(size_t)TOK * D_FF];
__device__ float  g_x1 [(size_t)TOK * D_MODEL];
__device__ __half g_wq [(size_t)D_MODEL * D_MODEL];
__device__ __half g_wk [(size_t)D_MODEL * D_MODEL];
__device__ __half g_wv [(size_t)D_MODEL * D_MODEL];
__device__ __half g_wo [(size_t)D_MODEL * D_MODEL];
__device__ __half g_w1 [(size_t)D_FF * D_MODEL];
__device__ __half g_w2 [(size_t)D_MODEL * D_FF];

// ================= cp.async =================
#define CP_ASYNC16(dst, src) \
    asm volatile("cp.async.cg.shared.global [%0], [%1], 16;" :: "r"(dst), "l"(src))
#define CP_COMMIT() asm volatile("cp.async.commit_group;")
#define CP_WAIT2()  asm volatile("cp.async.wait_group 2;")

__device__ __forceinline__ uint32_t smem_u32(const void* p) {
    uint32_t a;
    asm("{ .reg .u64 t; cvta.to.shared.u64 t, %1; cvt.u32.u64 %0, t; }" : "=r"(a) : "l"(p));
    return a;
}

// ============================================================
// fused weight fp32 -> fp16 conversion (single launch, all 6 weights)
// ============================================================
constexpr int NW1 = D_MODEL * D_MODEL;       // 1048576
constexpr int NW2 = D_FF * D_MODEL;          // 4194304
constexpr int NW_TOT = 4 * NW1 + 2 * NW2;    // 12582912

__global__ void __launch_bounds__(256) f2h_all_kernel(
    const float* __restrict__ wq, const float* __restrict__ wk,
    const float* __restrict__ wv, const float* __restrict__ wo,
    const float* __restrict__ w1, const float* __restrict__ w2)
{
    int e = (blockIdx.x * 256 + threadIdx.x) * 4;
    if (e >= NW_TOT) return;
    const float* s;
    __half* d;
    int off;
    if (e < 4 * NW1) {
        int seg = e >> 20;                    // NW1 = 1<<20
        off = e & (NW1 - 1);
        switch (seg) {
            case 0:  s = wq; break;
            case 1:  s = wk; break;
            case 2:  s = wv; break;
            default: s = wo; break;
        }
        __half* dst[4] = {g_wq, g_wk, g_wv, g_wo};
        d = dst[seg];
    } else if (e < 4 * NW1 + NW2) {
        s = w1; d = g_w1; off = e - 4 * NW1;
    } else {
        s = w2; d = g_w2; off = e - 4 * NW1 - NW2;
    }
    float4 v = *(const float4*)(s + off);
    union { __half2 h[2]; uint2 u; } c;
    c.h[0] = __floats2half2_rn(v.x, v.y);
    c.h[1] = __floats2half2_rn(v.z, v.w);
    *(uint2*)(d + off) = c.u;
}

// ============================================================
// LayerNorm (torch semantics: ddof=1, /(std+eps)) fp32 in -> fp16 out
// one block per row, 256 threads, D=1024 -> one float4 per thread
// ============================================================
__global__ void __launch_bounds__(256) ln_kernel(
    const float* __restrict__ x, const float* __restrict__ ga,
    const float* __restrict__ gb, __half* __restrict__ y)
{
    const int row = blockIdx.x;
    const float4 v = ((const float4*)(x + (size_t)row * D_MODEL))[threadIdx.x];

    __shared__ float red[32];
    const int lane = threadIdx.x & 31, wid = threadIdx.x >> 5;

    float s = v.x + v.y + v.z + v.w;
    #pragma unroll
    for (int o = 16; o; o >>= 1) s += __shfl_down_sync(0xffffffffu, s, o);
    if (lane == 0) red[wid] = s;
    __syncthreads();
    if (wid == 0) {
        float t = (lane < 8) ? red[lane] : 0.f;
        #pragma unroll
        for (int o = 4; o; o >>= 1) t += __shfl_down_sync(0xffffffffu, t, o);
        if (lane == 0) red[0] = t;
    }
    __syncthreads();
    const float mean = red[0] * (1.f / 1024.f);

    const float dx = v.x - mean, dy = v.y - mean, dz = v.z - mean, dw = v.w - mean;
    float s2 = dx*dx + dy*dy + dz*dz + dw*dw;
    #pragma unroll
    for (int o = 16; o; o >>= 1) s2 += __shfl_down_sync(0xffffffffu, s2, o);
    __syncthreads();
    if (lane == 0) red[wid] = s2;
    __syncthreads();
    if (wid == 0) {
        float t = (lane < 8) ? red[lane] : 0.f;
        #pragma unroll
        for (int o = 4; o; o >>= 1) t += __shfl_down_sync(0xffffffffu, t, o);
        if (lane == 0) red[0] = t;
    }
    __syncthreads();
    const float var = red[0] * (1.f / 1023.f);
    const float inv = 1.f / (sqrtf(var) + 1e-5f);
    const float a = ga[0] * inv, b0 = gb[0];

    union { __half2 h[2]; uint2 u; } c;
    c.h[0] = __floats2half2_rn(a*dx + b0, a*dy + b0);
    c.h[1] = __floats2half2_rn(a*dz + b0, a*dw + b0);
    ((uint2*)(y + (size_t)row * D_MODEL))[threadIdx.x] = c.u;
}

// ============================================================
// fp16 HMMA GEMM: CTA tile 128x128, BK=64, 3-stage cp.async pipeline.
// __launch_bounds__(256,2) pins regs<=128 so 2 CTAs/SM (measured-good config).
// EPI: 0 = fp16 out (+bias), 1 = fp16 out (+bias,relu), 2 = fp32 out (+bias,+resid)
// ============================================================
constexpr int BM = 128, BN = 128, BK = 64;
constexpr int LDS = 72;
constexpr int TILE_HALVES = 128 * LDS;
constexpr int STAGE_BYTES = 2 * TILE_HALVES * 2;          // A+B = 36864
constexpr int G_STAGES = 3;
constexpr int G_SMEM = G_STAGES * STAGE_BYTES;            // 110592

template<int EPI>
__global__ void __launch_bounds__(256, 2) gemm_h(
    const __half* __restrict__ A, const __half* __restrict__ W,
    const float* __restrict__ bias, const float* __restrict__ resid,
    float* __restrict__ Cf, __half* __restrict__ Ch, int N, int K)
{
    extern __shared__ __align__(16) char smraw[];
    __half* sm = (__half*)smraw;
    const uint32_t smb = smem_u32(sm);

    const int tid = threadIdx.x;
    const int m0 = blockIdx.y * BM, n0 = blockIdx.x * BN;
    const int KT = K >> 6;

    auto fill = [&](int kb) {
        const int st = kb % G_STAGES;
        const uint32_t sA = smb + st * STAGE_BYTES;
        const uint32_t sB = sA + TILE_HALVES * 2;
        const __half* gA = A + (size_t)m0 * K + kb * BK;
        const __half* gB = W + (size_t)n0 * K + kb * BK;
        #pragma unroll
        for (int i = 0; i < 4; i++) {
            int lin = i * 256 + tid, r = lin >> 3, c = lin & 7;
            CP_ASYNC16(sA + r * (LDS * 2) + c * 16, gA + (size_t)r * K + c * 8);
        }
        #pragma unroll
        for (int i = 0; i < 4; i++) {
            int lin = i * 256 + tid, r = lin >> 3, c = lin & 7;
            CP_ASYNC16(sB + r * (LDS * 2) + c * 16, gB + (size_t)r * K + c * 8);
        }
        CP_COMMIT();
    };

    const int warp = tid >> 5, wm = warp >> 1, wn = warp & 1;

    wmma::fragment<wmma::accumulator, 16, 16, 16, float> cf[2][4];
    #pragma unroll
    for (int i = 0; i < 2; i++)
        #pragma unroll
        for (int j = 0; j < 4; j++) wmma::fill_fragment(cf[i][j], 0.f);

    fill(0); fill(1); fill(2);

    for (int kb = 0; kb < KT; kb++) {
        const int st = kb % G_STAGES;
        CP_WAIT2();
        __syncthreads();

        const __half* As = sm + st * (STAGE_BYTES / 2) + (wm * 32) * LDS;
        const __half* Bs = sm + st * (STAGE_BYTES / 2) + TILE_HALVES + (wn * 64) * LDS;

        #pragma unroll
        for (int kk = 0; kk < 4; kk++) {
            wmma::fragment<wmma::matrix_a, 16, 16, 16, __half, wmma::row_major> af[2];
            #pragma unroll
            for (int mi = 0; mi < 2; mi++)
                wmma::load_matrix_sync(af[mi], As + (mi * 16) * LDS + kk * 16, LDS);
            #pragma unroll
            for (int nj = 0; nj < 4; nj++) {
                wmma::fragment<wmma::matrix_b, 16, 16, 16, __half, wmma::col_major> bf;
                wmma::load_matrix_sync(bf, Bs + (nj * 16) * LDS + kk * 16, LDS);
                #pragma unroll
                for (int mi = 0; mi < 2; mi++)
                    wmma::mma_sync(cf[mi][nj], af[mi], bf, cf[mi][nj]);
            }
        }
        __syncthreads();
        if (kb + G_STAGES < KT) fill(kb + G_STAGES); else CP_COMMIT();
    }

    // epilogue: stage accum to smem (reuse pipeline smem), then fused store
    float* Cs = (float*)sm;                    // 128 x 136 floats = 69632 B
    constexpr int LDC = 136;
    #pragma unroll
    for (int mi = 0; mi < 2; mi++)
        #pragma unroll
        for (int nj = 0; nj < 4; nj++)
            wmma::store_matrix_sync(Cs + (wm*32 + mi*16) * LDC + wn*64 + nj*16,
                                    cf[mi][nj], LDC, wmma::mem_row_major);
    __syncthreads();

    #pragma unroll
    for (int i = 0; i < 16; i++) {
        int lin = i * 256 + tid, r = lin >> 5, c4 = lin & 31;
        float4 v = *(float4*)(Cs + r * LDC + c4 * 4);
        float4 bv = *(const float4*)(bias + n0 + c4 * 4);
        v.x += bv.x; v.y += bv.y; v.z += bv.z; v.w += bv.w;
        if (EPI == 1) {
            v.x = fmaxf(v.x, 0.f); v.y = fmaxf(v.y, 0.f);
            v.z = fmaxf(v.z, 0.f); v.w = fmaxf(v.w, 0.f);
        }
        if (EPI == 2) {
            float4 rv = *(const float4*)(resid + (size_t)(m0 + r) * N + n0 + c4 * 4);
            v.x += rv.x; v.y += rv.y; v.z += rv.z; v.w += rv.w;
            *(float4*)(Cf + (size_t)(m0 + r) * N + n0 + c4 * 4) = v;
        } else {
            union { __half2 h[2]; uint2 u; } stv;
            stv.h[0] = __floats2half2_rn(v.x, v.y);
            stv.h[1] = __floats2half2_rn(v.z, v.w);
            *(uint2*)(Ch + (size_t)(m0 + r) * N + n0 + c4 * 4) = stv.u;
        }
    }
}

// ============================================================
// Flash attention: warp-local softmax + REGISTER-RESIDENT O accumulator.
// O rescale uses the sm80+ m16n16k16 f32 accumulator layout:
//   element i of lane l -> row (l>>2) + ((i&2)?8:0)
// fac per row fetched from softmax lanes via shfl (lane 2r owns local row r).
// smem: Qs/Ks/Vs/Ps (36.9KB) + Ss (17.4KB, reused for epilogue) = 54.3KB
//   -> 4 CTAs/SM; __launch_bounds__(128,4) caps regs at 128.
// ============================================================
constexpr int LDH = 72;   // half row stride (144 B)
constexpr int LDF = 68;   // float row stride (272 B)
constexpr int ATTN_SMEM = 4 * 64 * LDH * 2 + 64 * LDF * 4;  // 36864+17408 = 54272

__global__ void __launch_bounds__(128, 4) attn_kernel(
    const __half* __restrict__ Q, const __half* __restrict__ K,
    const __half* __restrict__ V, __half* __restrict__ O)
{
    extern __shared__ __align__(16) char sm[];
    __half* Qs = (__half*)(sm);
    __half* Ks = Qs + 64 * LDH;
    __half* Vs = Ks + 64 * LDH;
    __half* Ps = Vs + 64 * LDH;
    float*  Ss = (float*)(Ps + 64 * LDH);   // also reused as O staging in epilogue

    const int tid = threadIdx.x;
    const int w = tid >> 5, lane = tid & 31;
    const int b = blockIdx.y >> 4, h = blockIdx.y & 15;
    const size_t base = (size_t)b * SEQ * D_MODEL + (size_t)h * 64;
    const int q0 = blockIdx.x * 64;
    const __half2 qs2 = __floats2half2_rn(0.125f, 0.125f);

    // softmax-lane row assignment: 2 lanes per row, 32 cols each
    const int srow = w * 16 + (lane >> 1);   // global row in [0,64)
    const int hh = lane & 1;
    const int arow = lane >> 2;              // accumulator local base row (0..7)

    // load Q (scaled by exact 1/8)
    #pragma unroll
    for (int i = 0; i < 4; i++) {
        int lin = i * 128 + tid, r = lin >> 3, c = lin & 7;
        union { __half2 h[4]; uint4 u; } v;
        v.u = *(const uint4*)(Q + base + (size_t)(q0 + r) * D_MODEL + c * 8);
        #pragma unroll
        for (int t = 0; t < 4; t++) v.h[t] = __hmul2(v.h[t], qs2);
        *(uint4*)(Qs + r * LDH + c * 8) = v.u;
    }

    float m_reg = -1e30f, l_reg = 0.f;
    wmma::fragment<wmma::accumulator, 16, 16, 16, float> of[4];
    #pragma unroll
    for (int nj = 0; nj < 4; nj++) wmma::fill_fragment(of[nj], 0.f);

    for (int kt = 0; kt < SEQ / 64; kt++) {
        const int k0 = kt * 64;
        __syncthreads();   // all warps done with previous Ks/Vs
        #pragma unroll
        for (int i = 0; i < 4; i++) {
            int lin = i * 128 + tid, r = lin >> 3, c = lin & 7;
            *(uint4*)(Ks + r * LDH + c * 8) =
                *(const uint4*)(K + base + (size_t)(k0 + r) * D_MODEL + c * 8);
            *(uint4*)(Vs + r * LDH + c * 8) =
                *(const uint4*)(V + base + (size_t)(k0 + r) * D_MODEL + c * 8);
        }
        __syncthreads();

        // S = Qs * Ks^T  (warp w: rows [16w,16w+16) x 64 keys)
        {
            wmma::fragment<wmma::accumulator, 16, 16, 16, float> sf[4];
            #pragma unroll
            for (int nj = 0; nj < 4; nj++) wmma::fill_fragment(sf[nj], 0.f);
            #pragma unroll
            for (int kk = 0; kk < 4; kk++) {
                wmma::fragment<wmma::matrix_a, 16, 16, 16, __half, wmma::row_major> af;
                wmma::load_matrix_sync(af, Qs + (w * 16) * LDH + kk * 16, LDH);
                #pragma unroll
                for (int nj = 0; nj < 4; nj++) {
                    wmma::fragment<wmma::matrix_b, 16, 16, 16, __half, wmma::col_major> bf;
                    wmma::load_matrix_sync(bf, Ks + (nj * 16) * LDH + kk * 16, LDH);
                    wmma::mma_sync(sf[nj], af, bf, sf[nj]);
                }
            }
            #pragma unroll
            for (int nj = 0; nj < 4; nj++)
                wmma::store_matrix_sync(Ss + (w * 16) * LDF + nj * 16, sf[nj], LDF,
                                        wmma::mem_row_major);
        }
        __syncwarp();

        // warp-local online softmax (vectorized), m/l in registers
        float fac;
        {
            const float4* sr4 = (const float4*)(Ss + srow * LDF + hh * 32);
            float mx = -1e30f;
            #pragma unroll
            for (int j = 0; j < 8; j++) {
                float4 v = sr4[j];
                mx = fmaxf(mx, fmaxf(fmaxf(v.x, v.y), fmaxf(v.z, v.w)));
            }
            mx = fmaxf(mx, __shfl_xor_sync(0xffffffffu, mx, 1));
            const float mnew = fmaxf(m_reg, mx);
            fac = __expf(m_reg - mnew);
            float ssum = 0.f;
            uint2* pr = (uint2*)(Ps + srow * LDH + hh * 32);
            #pragma unroll
            for (int j = 0; j < 8; j++) {
                float4 v = sr4[j];
                float e0 = __expf(v.x - mnew), e1 = __expf(v.y - mnew);
                float e2 = __expf(v.z - mnew), e3 = __expf(v.w - mnew);
                ssum += (e0 + e1) + (e2 + e3);
                union { __half2 h[2]; uint2 u; } pk;
                pk.h[0] = __floats2half2_rn(e0, e1);
                pk.h[1] = __floats2half2_rn(e2, e3);
                pr[j] = pk.u;
            }
            ssum += __shfl_xor_sync(0xffffffffu, ssum, 1);
            l_reg = l_reg * fac + ssum;
            m_reg = mnew;
        }

        // fetch per-row rescale factors for this lane's accumulator rows
        const float fac_a = __shfl_sync(0xffffffffu, fac, arow << 1);
        const float fac_b = __shfl_sync(0xffffffffu, fac, (arow + 8) << 1);

        // rescale O accumulator registers (row = arow + ((i&2)?8:0))
        #pragma unroll
        for (int nj = 0; nj < 4; nj++) {
            #pragma unroll
            for (int i = 0; i < 8; i++)
                of[nj].x[i] *= (i & 2) ? fac_b : fac_a;
        }
        __syncwarp();   // P writes visible before fragment loads

        // O += P * V  (kk-outer: P frag loaded once per kk)
        #pragma unroll
        for (int kk = 0; kk < 4; kk++) {
            wmma::fragment<wmma::matrix_a, 16, 16, 16, __half, wmma::row_major> af;
            wmma::load_matrix_sync(af, Ps + (w * 16) * LDH + kk * 16, LDH);
            #pragma unroll
            for (int nj = 0; nj < 4; nj++) {
                wmma::fragment<wmma::matrix_b, 16, 16, 16, __half, wmma::row_major> bf;
                wmma::load_matrix_sync(bf, Vs + (kk * 16) * LDH + nj * 16, LDH);
                wmma::mma_sync(of[nj], af, bf, of[nj]);
            }
        }
    }

    // epilogue: stage O frags to smem (Ss reuse), normalize, store fp16
    __syncthreads();
    #pragma unroll
    for (int nj = 0; nj < 4; nj++)
        wmma::store_matrix_sync(Ss + (w * 16) * LDF + nj * 16, of[nj], LDF,
                                wmma::mem_row_major);
    __syncwarp();
    {
        const float inv = 1.f / l_reg;
        const float4* orow = (const float4*)(Ss + srow * LDF + hh * 32);
        #pragma unroll
        for (int c4 = 0; c4 < 8; c4++) {
            float4 v = orow[c4];
            union { __half2 h[2]; uint2 u; } st;
            st.h[0] = __floats2half2_rn(v.x * inv, v.y * inv);
            st.h[1] = __floats2half2_rn(v.z * inv, v.w * inv);
            *(uint2*)(O + base + (size_t)(q0 + srow) * D_MODEL + hh * 32 + c4 * 4) = st.u;
        }
    }
}

// ============================================================
// launcher
// ============================================================
extern "C" void kernel_launch(void* const* d_in, const int* in_sizes, int n_in,
                              void* d_out, int out_size)
{
    const float* x    = (const float*)d_in[0];
    const float* wq   = (const float*)d_in[2];
    const float* bq   = (const float*)d_in[3];
    const float* wk   = (const float*)d_in[4];
    const float* bk   = (const float*)d_in[5];
    const float* wv   = (const float*)d_in[6];
    const float* bv   = (const float*)d_in[7];
    const float* wo   = (const float*)d_in[8];
    const float* bo   = (const float*)d_in[9];
    const float* w1   = (const float*)d_in[10];
    const float* b1   = (const float*)d_in[11];
    const float* w2   = (const float*)d_in[12];
    const float* b2   = (const float*)d_in[13];
    const float* ln1a = (const float*)d_in[14];
    const float* ln1b = (const float*)d_in[15];
    const float* ln2a = (const float*)d_in[16];
    const float* ln2b = (const float*)d_in[17];
    float* out = (float*)d_out;

    void* p;
    cudaGetSymbolAddress(&p, g_h);   __half* h   = (__half*)p;
    cudaGetSymbolAddress(&p, g_q);   __half* q   = (__half*)p;
    cudaGetSymbolAddress(&p, g_k);   __half* k   = (__half*)p;
    cudaGetSymbolAddress(&p, g_v);   __half* v   = (__half*)p;
    cudaGetSymbolAddress(&p, g_ctx); __half* ctx = (__half*)p;
    cudaGetSymbolAddress(&p, g_f1);  __half* f1  = (__half*)p;
    cudaGetSymbolAddress(&p, g_x1);  float*  x1  = (float*)p;

    cudaFuncSetAttribute(gemm_h<0>, cudaFuncAttributeMaxDynamicSharedMemorySize, G_SMEM);
    cudaFuncSetAttribute(gemm_h<1>, cudaFuncAttributeMaxDynamicSharedMemorySize, G_SMEM);
    cudaFuncSetAttribute(gemm_h<2>, cudaFuncAttributeMaxDynamicSharedMemorySize, G_SMEM);
    cudaFuncSetAttribute(attn_kernel, cudaFuncAttributeMaxDynamicSharedMemorySize, ATTN_SMEM);

    __half* wqh; __half* wkh; __half* wvh; __half* woh; __half* w1h; __half* w2h;
    cudaGetSymbolAddress(&p, g_wq); wqh = (__half*)p;
    cudaGetSymbolAddress(&p, g_wk); wkh = (__half*)p;
    cudaGetSymbolAddress(&p, g_wv); wvh = (__half*)p;
    cudaGetSymbolAddress(&p, g_wo); woh = (__half*)p;
    cudaGetSymbolAddress(&p, g_w1); w1h = (__half*)p;
    cudaGetSymbolAddress(&p, g_w2); w2h = (__half*)p;

    // all weights -> fp16 (single launch)
    f2h_all_kernel<<<NW_TOT / 1024, 256>>>(wq, wk, wv, wo, w1, w2);

    // LN1 -> h (fp16)
    ln_kernel<<<TOK, 256>>>(x, ln1a, ln1b, h);

    // QKV projections (fp16 out)
    dim3 g1024(D_MODEL / 128, TOK / 128);
    gemm_h<0><<<g1024, 256, G_SMEM>>>(h, wqh, bq, nullptr, nullptr, q, D_MODEL, D_MODEL);
    gemm_h<0><<<g1024, 256, G_SMEM>>>(h, wkh, bk, nullptr, nullptr, k, D_MODEL, D_MODEL);
    gemm_h<0><<<g1024, 256, G_SMEM>>>(h, wvh, bv, nullptr, nullptr, v, D_MODEL, D_MODEL);

    // attention -> ctx (fp16)
    attn_kernel<<<dim3(SEQ / 64, BATCH * N_HEADS), 128, ATTN_SMEM>>>(q, k, v, ctx);

    // W_O + residual -> x1 (fp32)
    gemm_h<2><<<g1024, 256, G_SMEM>>>(ctx, woh, bo, x, x1, nullptr, D_MODEL, D_MODEL);

    // LN2 -> h (fp16)
    ln_kernel<<<TOK, 256>>>(x1, ln2a, ln2b, h);

    // FFN
    gemm_h<1><<<dim3(D_FF / 128, TOK / 128), 256, G_SMEM>>>(h, w1h, b1, nullptr, nullptr, f1, D_FF, D_MODEL);
    gemm_h<2><<<g1024, 256, G_SMEM>>>(f1, w2h, b2, x1, out, nullptr, D_MODEL, D_FF);
}